// round 1
// baseline (speedup 1.0000x reference)
#include <cuda_runtime.h>
#include <cuda_bf16.h>
#include <cstddef>

// Problem constants
#define MB 8
#define TT 2048
#define CC 1024
#define MROWS (MB*TT)          // 16384
#define BTC (MROWS*CC)         // 16,777,216
#define BT4C (MROWS*4*CC)      // 67,108,864

// Scratch (static device globals; no runtime allocation)
__device__ float g_h [BTC];
__device__ float g_k [BTC];
__device__ float g_v [BTC];
__device__ float g_r [BTC];
__device__ float g_x2[BTC];
__device__ float g_h2[BTC];
__device__ float g_s [BTC];
__device__ float g_kk[BT4C];

// ---------------------------------------------------------------------------
// LayerNorm: one 256-thread block per row of C=1024 (float4 per thread)
// ---------------------------------------------------------------------------
__global__ void __launch_bounds__(256) ln_kernel(
    const float* __restrict__ x, const float* __restrict__ g,
    const float* __restrict__ b, float* __restrict__ out)
{
    const int C = CC;
    size_t row = blockIdx.x;
    const float4* xr = (const float4*)(x + row * C);
    int tid = threadIdx.x;
    float4 v = xr[tid];

    float s = v.x + v.y + v.z + v.w;
    #pragma unroll
    for (int o = 16; o > 0; o >>= 1) s += __shfl_xor_sync(0xffffffffu, s, o);
    __shared__ float ws[8];
    if ((tid & 31) == 0) ws[tid >> 5] = s;
    __syncthreads();
    float mu = (ws[0]+ws[1]+ws[2]+ws[3]+ws[4]+ws[5]+ws[6]+ws[7]) * (1.0f / C);
    __syncthreads();

    float dx = v.x - mu, dy = v.y - mu, dz = v.z - mu, dw = v.w - mu;
    float s2 = dx*dx + dy*dy + dz*dz + dw*dw;
    #pragma unroll
    for (int o = 16; o > 0; o >>= 1) s2 += __shfl_xor_sync(0xffffffffu, s2, o);
    if ((tid & 31) == 0) ws[tid >> 5] = s2;
    __syncthreads();
    float var = (ws[0]+ws[1]+ws[2]+ws[3]+ws[4]+ws[5]+ws[6]+ws[7]) * (1.0f / C);
    float rstd = rsqrtf(var + 1e-5f);

    float4 gv = ((const float4*)g)[tid];
    float4 bv = ((const float4*)b)[tid];
    float4 o;
    o.x = dx * rstd * gv.x + bv.x;
    o.y = dy * rstd * gv.y + bv.y;
    o.z = dz * rstd * gv.z + bv.z;
    o.w = dw * rstd * gv.w + bv.w;
    ((float4*)(out + row * C))[tid] = o;
}

// ---------------------------------------------------------------------------
// WKV sequential scan: one thread per (b, c) channel, fused x + r*y epilogue.
// Replicates the reference recurrence exactly.
// ---------------------------------------------------------------------------
__global__ void __launch_bounds__(256) wkv_kernel(
    const float* __restrict__ kp, const float* __restrict__ vp,
    const float* __restrict__ rp, const float* __restrict__ xp,
    const float* __restrict__ wdec, const float* __restrict__ ufst,
    float* __restrict__ out)
{
    int gid = blockIdx.x * 256 + threadIdx.x;   // 0..8191
    int b = gid >> 10;
    int c = gid & (CC - 1);
    float w = wdec[c], u = ufst[c];
    float aa = 0.0f, bb = 0.0f, pp = -1e38f;
    size_t idx = ((size_t)b * TT) * CC + c;
    #pragma unroll 2
    for (int t = 0; t < TT; t++, idx += CC) {
        float kk = kp[idx];
        float vv = vp[idx];
        float rr = rp[idx];
        float xx = xp[idx];
        float uk = u + kk;
        float p  = fmaxf(pp, uk);
        float e1 = __expf(pp - p);
        float e2 = __expf(uk - p);
        float y  = (e1 * aa + e2 * vv) / (e1 + e2);
        out[idx] = xx + rr * y;
        float pw = pp + w;
        float wk = w + kk;
        float p2 = fmaxf(pw, wk);
        float e1u = __expf(pw - p2);
        float e2u = __expf(wk - p2);
        aa = e1u * aa + e2u * vv;
        bb = e1u + e2u;
        pp = p2 + __logf(bb);
    }
}

// ---------------------------------------------------------------------------
// Tiled SGEMM: C[M,N] = epi(A'[M,K] @ B[K,N]) where A' optionally applies the
// RWKV token-shift mix on the fly: A'[m,k] = A[m,k]*mix[k] + A[m-1,k]*(1-mix[k])
// (zero row when m is the first token of a batch).
// BM=BN=128, BK=16, 256 threads, 8x8 per thread.
// ---------------------------------------------------------------------------
#define BM 128
#define BN 128
#define BK 16
#define TM 8
#define TN 8

#define EPI_NONE 0
#define EPI_SIGMOID 1
#define EPI_RELUSQ 2
#define EPI_RESID 3

template <int EPI, bool MIX>
__global__ void __launch_bounds__(256, 2) gemm_kernel(
    const float* __restrict__ A, const float* __restrict__ Bw,
    float* __restrict__ Cc,
    const float* __restrict__ mix,
    const float* __restrict__ resid, const float* __restrict__ gate,
    int M, int N, int K)
{
    __shared__ float As[BK * BM];
    __shared__ float Bs[BK * BN];

    int tid = threadIdx.x;
    int m0 = blockIdx.y * BM;
    int n0 = blockIdx.x * BN;
    int tr = tid >> 4;   // 0..15
    int tc = tid & 15;   // 0..15

    float acc[TM][TN];
    #pragma unroll
    for (int i = 0; i < TM; i++)
        #pragma unroll
        for (int j = 0; j < TN; j++) acc[i][j] = 0.0f;

    for (int k0 = 0; k0 < K; k0 += BK) {
        // ---- load A tile (128 rows x 16 k), optionally blended with shifted row
        #pragma unroll
        for (int l = 0; l < 2; l++) {
            int i = tid + l * 256;        // float4 index, 512 total
            int row = i >> 2;             // 0..127
            int c4  = i & 3;              // 0..3
            int gr = m0 + row;
            int gk = k0 + c4 * 4;
            float4 hv = *(const float4*)(A + (size_t)gr * K + gk);
            if (MIX) {
                int t = gr & (TT - 1);    // token index within batch
                float4 hp = make_float4(0.f, 0.f, 0.f, 0.f);
                if (t > 0) hp = *(const float4*)(A + (size_t)(gr - 1) * K + gk);
                float4 mx = *(const float4*)(mix + gk);
                hv.x = hv.x * mx.x + hp.x * (1.0f - mx.x);
                hv.y = hv.y * mx.y + hp.y * (1.0f - mx.y);
                hv.z = hv.z * mx.z + hp.z * (1.0f - mx.z);
                hv.w = hv.w * mx.w + hp.w * (1.0f - mx.w);
            }
            As[(c4 * 4 + 0) * BM + row] = hv.x;
            As[(c4 * 4 + 1) * BM + row] = hv.y;
            As[(c4 * 4 + 2) * BM + row] = hv.z;
            As[(c4 * 4 + 3) * BM + row] = hv.w;
        }
        // ---- load B tile (16 rows x 128 n)
        #pragma unroll
        for (int l = 0; l < 2; l++) {
            int i = tid + l * 256;
            int row = i >> 5;             // 0..15
            int c4  = i & 31;             // 0..31
            float4 bv = *(const float4*)(Bw + (size_t)(k0 + row) * N + n0 + c4 * 4);
            *(float4*)(Bs + row * BN + c4 * 4) = bv;
        }
        __syncthreads();

        #pragma unroll
        for (int kk = 0; kk < BK; kk++) {
            float ra[TM], rb[TN];
            #pragma unroll
            for (int i = 0; i < TM; i += 4)
                *(float4*)(ra + i) = *(const float4*)(As + kk * BM + tr * TM + i);
            #pragma unroll
            for (int j = 0; j < TN; j += 4)
                *(float4*)(rb + j) = *(const float4*)(Bs + kk * BN + tc * TN + j);
            #pragma unroll
            for (int i = 0; i < TM; i++)
                #pragma unroll
                for (int j = 0; j < TN; j++)
                    acc[i][j] = fmaf(ra[i], rb[j], acc[i][j]);
        }
        __syncthreads();
    }

    // ---- epilogue
    #pragma unroll
    for (int i = 0; i < TM; i++) {
        int gm = m0 + tr * TM + i;
        #pragma unroll
        for (int j = 0; j < TN; j += 4) {
            int gn = n0 + tc * TN + j;
            size_t idx = (size_t)gm * N + gn;
            float4 o;
            o.x = acc[i][j + 0];
            o.y = acc[i][j + 1];
            o.z = acc[i][j + 2];
            o.w = acc[i][j + 3];
            if (EPI == EPI_SIGMOID) {
                o.x = 1.0f / (1.0f + __expf(-o.x));
                o.y = 1.0f / (1.0f + __expf(-o.y));
                o.z = 1.0f / (1.0f + __expf(-o.z));
                o.w = 1.0f / (1.0f + __expf(-o.w));
            } else if (EPI == EPI_RELUSQ) {
                float a0 = fmaxf(o.x, 0.f), a1 = fmaxf(o.y, 0.f);
                float a2 = fmaxf(o.z, 0.f), a3 = fmaxf(o.w, 0.f);
                o.x = a0 * a0; o.y = a1 * a1; o.z = a2 * a2; o.w = a3 * a3;
            } else if (EPI == EPI_RESID) {
                float4 rz = *(const float4*)(resid + idx);
                float4 gz = *(const float4*)(gate + idx);
                o.x = rz.x + gz.x * o.x;
                o.y = rz.y + gz.y * o.y;
                o.z = rz.z + gz.z * o.z;
                o.w = rz.w + gz.w * o.w;
            }
            *(float4*)(Cc + idx) = o;
        }
    }
}

// ---------------------------------------------------------------------------
// Host launcher
// ---------------------------------------------------------------------------
static float* symaddr(const void* sym)
{
    void* p = nullptr;
    cudaGetSymbolAddress(&p, sym);
    return (float*)p;
}

extern "C" void kernel_launch(void* const* d_in, const int* in_sizes, int n_in,
                              void* d_out, int out_size)
{
    const float* x      = (const float*)d_in[0];
    const float* tdecay = (const float*)d_in[1];
    const float* tfirst = (const float*)d_in[2];
    const float* w_tk   = (const float*)d_in[3];
    const float* w_tv   = (const float*)d_in[4];
    const float* w_tr   = (const float*)d_in[5];
    const float* w_ck   = (const float*)d_in[6];
    const float* w_cv   = (const float*)d_in[7];
    const float* w_cr   = (const float*)d_in[8];
    const float* ln1_g  = (const float*)d_in[9];
    const float* ln1_b  = (const float*)d_in[10];
    const float* ln2_g  = (const float*)d_in[11];
    const float* ln2_b  = (const float*)d_in[12];
    const float* mix_k  = (const float*)d_in[13];
    const float* mix_v  = (const float*)d_in[14];
    const float* mix_r  = (const float*)d_in[15];
    const float* cmix_k = (const float*)d_in[16];
    const float* cmix_r = (const float*)d_in[17];
    float* out = (float*)d_out;

    float* h  = symaddr(g_h);
    float* k  = symaddr(g_k);
    float* v  = symaddr(g_v);
    float* r  = symaddr(g_r);
    float* x2 = symaddr(g_x2);
    float* h2 = symaddr(g_h2);
    float* s  = symaddr(g_s);
    float* kk = symaddr(g_kk);

    const int M = MROWS;
    dim3 gC(CC / BN, M / BM);       // (8, 128) for N=1024
    dim3 g4C(4 * CC / BN, M / BM);  // (32, 128) for N=4096

    // 1) h = LN1(x)
    ln_kernel<<<M, 256>>>(x, ln1_g, ln1_b, h);

    // 2-4) k, v, r = mix-shift(h) @ W  (r with sigmoid)
    gemm_kernel<EPI_NONE,    true><<<gC, 256>>>(h, w_tk, k, mix_k, nullptr, nullptr, M, CC, CC);
    gemm_kernel<EPI_NONE,    true><<<gC, 256>>>(h, w_tv, v, mix_v, nullptr, nullptr, M, CC, CC);
    gemm_kernel<EPI_SIGMOID, true><<<gC, 256>>>(h, w_tr, r, mix_r, nullptr, nullptr, M, CC, CC);

    // 5) x2 = x + r * WKV(k, v)
    wkv_kernel<<<(MB * CC) / 256, 256>>>(k, v, r, x, tdecay, tfirst, x2);

    // 6) h2 = LN2(x2)
    ln_kernel<<<M, 256>>>(x2, ln2_g, ln2_b, h2);

    // 7) kk = relu(mix-shift(h2) @ w_ck)^2        [M, 4096]
    gemm_kernel<EPI_RELUSQ,  true><<<g4C, 256>>>(h2, w_ck, kk, cmix_k, nullptr, nullptr, M, 4 * CC, CC);

    // 8) s = sigmoid(mix-shift(h2) @ w_cr)
    gemm_kernel<EPI_SIGMOID, true><<<gC, 256>>>(h2, w_cr, s, cmix_r, nullptr, nullptr, M, CC, CC);

    // 9) out = x2 + s * (kk @ w_cv)
    gemm_kernel<EPI_RESID,  false><<<gC, 256>>>(kk, w_cv, out, nullptr, x2, s, M, CC, 4 * CC);
}

// round 3
// speedup vs baseline: 2.3231x; 2.3231x over previous
#include <cuda_runtime.h>
#include <cstdint>
#include <cstddef>

// Problem constants
#define MB 8
#define TT 2048
#define CC 1024
#define MROWS (MB*TT)          // 16384
#define BTC (MROWS*CC)
#define BT4C (MROWS*4*CC)

// Scratch (static device globals; no runtime allocation)
__device__ float g_h  [BTC];
__device__ float g_xk [BTC];
__device__ float g_xv [BTC];
__device__ float g_xr [BTC];
__device__ float g_k  [BTC];
__device__ float g_v  [BTC];
__device__ float g_r  [BTC];
__device__ float g_x2 [BTC];
__device__ float g_h2 [BTC];
__device__ float g_ck [BTC];
__device__ float g_cr [BTC];
__device__ float g_s  [BTC];
__device__ float g_kk [BT4C];
__device__ float g_wtkT[CC*CC];
__device__ float g_wtvT[CC*CC];
__device__ float g_wtrT[CC*CC];
__device__ float g_wcrT[CC*CC];
__device__ float g_wckT[4*CC*CC];
__device__ float g_wcvT[4*CC*CC];

// ---------------------------------------------------------------------------
// Helpers
// ---------------------------------------------------------------------------
__device__ __forceinline__ uint32_t smem_u32(const void* p){
    uint32_t a;
    asm("{ .reg .u64 t; cvta.to.shared.u64 t, %1; cvt.u32.u64 %0, t; }" : "=r"(a) : "l"(p));
    return a;
}
__device__ __forceinline__ void cp16(uint32_t dst, const void* src){
    asm volatile("cp.async.ca.shared.global [%0], [%1], 16;" :: "r"(dst), "l"(src));
}
#define CP_COMMIT() asm volatile("cp.async.commit_group;" ::: "memory")
#define CP_WAIT2()  asm volatile("cp.async.wait_group 2;" ::: "memory")

__device__ __forceinline__ void mma_tf32(float* d, const uint32_t* a, const uint32_t* b){
    asm volatile("mma.sync.aligned.m16n8k8.row.col.f32.tf32.tf32.f32 "
        "{%0,%1,%2,%3}, {%4,%5,%6,%7}, {%8,%9}, {%0,%1,%2,%3};"
        : "+f"(d[0]), "+f"(d[1]), "+f"(d[2]), "+f"(d[3])
        : "r"(a[0]), "r"(a[1]), "r"(a[2]), "r"(a[3]), "r"(b[0]), "r"(b[1]));
}
__device__ __forceinline__ uint32_t lds32(uint32_t addr){
    uint32_t v;
    asm volatile("ld.shared.b32 %0, [%1];" : "=r"(v) : "r"(addr));
    return v;
}

// ---------------------------------------------------------------------------
// LayerNorm: one 256-thread block per row of C=1024
// ---------------------------------------------------------------------------
__global__ void __launch_bounds__(256) ln_kernel(
    const float* __restrict__ x, const float* __restrict__ g,
    const float* __restrict__ b, float* __restrict__ out)
{
    const int C = CC;
    size_t row = blockIdx.x;
    const float4* xr = (const float4*)(x + row * C);
    int tid = threadIdx.x;
    float4 v = xr[tid];

    float s = v.x + v.y + v.z + v.w;
    #pragma unroll
    for (int o = 16; o > 0; o >>= 1) s += __shfl_xor_sync(0xffffffffu, s, o);
    __shared__ float ws[8];
    if ((tid & 31) == 0) ws[tid >> 5] = s;
    __syncthreads();
    float mu = (ws[0]+ws[1]+ws[2]+ws[3]+ws[4]+ws[5]+ws[6]+ws[7]) * (1.0f / C);
    __syncthreads();

    float dx = v.x - mu, dy = v.y - mu, dz = v.z - mu, dw = v.w - mu;
    float s2 = dx*dx + dy*dy + dz*dz + dw*dw;
    #pragma unroll
    for (int o = 16; o > 0; o >>= 1) s2 += __shfl_xor_sync(0xffffffffu, s2, o);
    if ((tid & 31) == 0) ws[tid >> 5] = s2;
    __syncthreads();
    float var = (ws[0]+ws[1]+ws[2]+ws[3]+ws[4]+ws[5]+ws[6]+ws[7]) * (1.0f / C);
    float rstd = rsqrtf(var + 1e-5f);

    float4 gv = ((const float4*)g)[tid];
    float4 bv = ((const float4*)b)[tid];
    float4 o;
    o.x = dx * rstd * gv.x + bv.x;
    o.y = dy * rstd * gv.y + bv.y;
    o.z = dz * rstd * gv.z + bv.z;
    o.w = dw * rstd * gv.w + bv.w;
    ((float4*)(out + row * C))[tid] = o;
}

// ---------------------------------------------------------------------------
// Token-shift mix kernels: x' = h*mix + h_prev*(1-mix); h_prev zero at t==0.
// ---------------------------------------------------------------------------
__device__ __forceinline__ float4 mixf4(float4 h, float4 hp, float4 m){
    float4 o;
    o.x = h.x*m.x + hp.x*(1.f-m.x);
    o.y = h.y*m.y + hp.y*(1.f-m.y);
    o.z = h.z*m.z + hp.z*(1.f-m.z);
    o.w = h.w*m.w + hp.w*(1.f-m.w);
    return o;
}
__global__ void __launch_bounds__(256) mix3_kernel(
    const float* __restrict__ h, const float* __restrict__ mk,
    const float* __restrict__ mv, const float* __restrict__ mr,
    float* __restrict__ xk, float* __restrict__ xv, float* __restrict__ xr)
{
    int j = blockIdx.x * 256 + threadIdx.x;   // float4 index
    int row = j >> 8;                          // CC/4 = 256 float4 per row
    int c4  = j & 255;
    float4 hv = ((const float4*)h)[j];
    float4 hp = make_float4(0.f,0.f,0.f,0.f);
    if ((row & (TT-1)) != 0) hp = ((const float4*)h)[j - 256];
    ((float4*)xk)[j] = mixf4(hv, hp, ((const float4*)mk)[c4]);
    ((float4*)xv)[j] = mixf4(hv, hp, ((const float4*)mv)[c4]);
    ((float4*)xr)[j] = mixf4(hv, hp, ((const float4*)mr)[c4]);
}
__global__ void __launch_bounds__(256) mix2_kernel(
    const float* __restrict__ h, const float* __restrict__ mk,
    const float* __restrict__ mr,
    float* __restrict__ xk, float* __restrict__ xr)
{
    int j = blockIdx.x * 256 + threadIdx.x;
    int row = j >> 8;
    int c4  = j & 255;
    float4 hv = ((const float4*)h)[j];
    float4 hp = make_float4(0.f,0.f,0.f,0.f);
    if ((row & (TT-1)) != 0) hp = ((const float4*)h)[j - 256];
    ((float4*)xk)[j] = mixf4(hv, hp, ((const float4*)mk)[c4]);
    ((float4*)xr)[j] = mixf4(hv, hp, ((const float4*)mr)[c4]);
}

// ---------------------------------------------------------------------------
// WKV sequential scan: one thread per (b, c) channel, fused x + r*y epilogue.
// ---------------------------------------------------------------------------
__global__ void __launch_bounds__(256) wkv_kernel(
    const float* __restrict__ kp, const float* __restrict__ vp,
    const float* __restrict__ rp, const float* __restrict__ xp,
    const float* __restrict__ wdec, const float* __restrict__ ufst,
    float* __restrict__ out)
{
    int gid = blockIdx.x * 256 + threadIdx.x;   // 0..8191
    int b = gid >> 10;
    int c = gid & (CC - 1);
    float w = wdec[c], u = ufst[c];
    float aa = 0.0f, bb = 0.0f, pp = -1e38f;
    size_t idx = ((size_t)b * TT) * CC + c;
    #pragma unroll 2
    for (int t = 0; t < TT; t++, idx += CC) {
        float kk = kp[idx];
        float vv = vp[idx];
        float rr = rp[idx];
        float xx = xp[idx];
        float uk = u + kk;
        float p  = fmaxf(pp, uk);
        float e1 = __expf(pp - p);
        float e2 = __expf(uk - p);
        float y  = (e1 * aa + e2 * vv) / (e1 + e2);
        out[idx] = xx + rr * y;
        float pw = pp + w;
        float wk = w + kk;
        float p2 = fmaxf(pw, wk);
        float e1u = __expf(pw - p2);
        float e2u = __expf(wk - p2);
        aa = e1u * aa + e2u * vv;
        bb = e1u + e2u;
        pp = p2 + __logf(bb);
    }
}

// ---------------------------------------------------------------------------
// Weight transpose: src[R, Ccols] -> dst[Ccols, R]
// ---------------------------------------------------------------------------
__global__ void __launch_bounds__(256) transpose_kernel(
    const float* __restrict__ src, float* __restrict__ dst, int R, int Ccols)
{
    __shared__ float t[32][33];
    int r0 = blockIdx.y * 32, c0 = blockIdx.x * 32;
    int tx = threadIdx.x, ty = threadIdx.y;
    #pragma unroll
    for (int j = 0; j < 32; j += 8)
        t[ty + j][tx] = src[(size_t)(r0 + ty + j) * Ccols + c0 + tx];
    __syncthreads();
    #pragma unroll
    for (int j = 0; j < 32; j += 8)
        dst[(size_t)(c0 + ty + j) * R + r0 + tx] = t[tx][ty + j];
}

// ---------------------------------------------------------------------------
// tf32 mma.sync GEMM: C[M,N] = epi(A[M,K] @ Bt[N,K]^T), both K-major fp32.
// CTA tile 256x128, BK=16, 3-stage cp.async pipeline, warp tile 64x64.
// Smem XOR-swizzled for conflict-free fragment reads.
// ---------------------------------------------------------------------------
#define CTM 256
#define CTN 128
#define GBK 16
#define A_BYTES (CTM*GBK*4)              // 16384
#define B_BYTES (CTN*GBK*4)              // 8192
#define STAGE_BYTES (A_BYTES + B_BYTES)  // 24576
#define GSMEM (STAGE_BYTES*3)            // 73728

#define EPI_NONE 0
#define EPI_SIGMOID 1
#define EPI_RELUSQ 2
#define EPI_RESID 3

template<int EPI>
__global__ void __launch_bounds__(256, 1) mma_gemm(
    const float* __restrict__ A, const float* __restrict__ Bt,
    float* __restrict__ Cc,
    const float* __restrict__ resid, const float* __restrict__ gate,
    int M, int N, int K)
{
    extern __shared__ char smem[];
    const uint32_t sbase = smem_u32(smem);
    const int tid = threadIdx.x;
    const int lane = tid & 31, wid = tid >> 5;
    const int wm = wid & 3, wn = wid >> 2;           // warp grid 4x2
    const int m0 = blockIdx.y * CTM, n0 = blockIdx.x * CTN;
    const int NS = K / GBK;

    // stage loader (cp.async, swizzled stores)
    auto load_stage = [&](int s, int buf){
        const int k0 = s * GBK;
        uint32_t sA = sbase + (uint32_t)buf * STAGE_BYTES;
        uint32_t sB = sA + A_BYTES;
        #pragma unroll
        for (int l = 0; l < 4; l++) {
            int j = l*256 + tid;                 // 0..1023 float4s of A tile
            int row = j >> 2, k4 = j & 3;
            const float* src = A + (size_t)(m0 + row) * K + k0 + k4*4;
            uint32_t dst = sA + (uint32_t)(row*64) + (uint32_t)((k4 ^ ((row>>1)&3)) * 16);
            cp16(dst, src);
        }
        #pragma unroll
        for (int l = 0; l < 2; l++) {
            int j = l*256 + tid;                 // 0..511 float4s of B tile
            int row = j >> 2, k4 = j & 3;
            const float* src = Bt + (size_t)(n0 + row) * K + k0 + k4*4;
            uint32_t dst = sB + (uint32_t)(row*64) + (uint32_t)((k4 ^ ((row>>1)&3)) * 16);
            cp16(dst, src);
        }
    };

    float acc[4][8][4];
    #pragma unroll
    for (int mi = 0; mi < 4; mi++)
        #pragma unroll
        for (int ni = 0; ni < 8; ni++)
            #pragma unroll
            for (int c = 0; c < 4; c++) acc[mi][ni][c] = 0.0f;

    load_stage(0, 0); CP_COMMIT();
    load_stage(1, 1); CP_COMMIT();
    load_stage(2, 2); CP_COMMIT();

    const int q    = (lane >> 3) & 3;
    const int colk = lane & 3;
    const uint32_t a_row_off = (uint32_t)((wm*64 + (lane>>2)) * 64);  // bytes
    const uint32_t b_row_off = (uint32_t)((wn*64 + (lane>>2)) * 64);

    int buf = 0;
    for (int s = 0; s < NS; s++) {
        CP_WAIT2();
        __syncthreads();
        uint32_t sA = sbase + (uint32_t)buf * STAGE_BYTES;
        uint32_t sB = sA + A_BYTES;
        #pragma unroll
        for (int ks = 0; ks < 2; ks++) {
            uint32_t ka0 = (uint32_t)((colk + 4*((2*ks + 0) ^ q)) * 4);
            uint32_t ka1 = (uint32_t)((colk + 4*((2*ks + 1) ^ q)) * 4);
            uint32_t a[4][4];
            #pragma unroll
            for (int mi = 0; mi < 4; mi++) {
                uint32_t base = sA + a_row_off + (uint32_t)(mi * 16 * 64);
                a[mi][0] = lds32(base + ka0);
                a[mi][1] = lds32(base + 8*64 + ka0);
                a[mi][2] = lds32(base + ka1);
                a[mi][3] = lds32(base + 8*64 + ka1);
            }
            uint32_t b[8][2];
            #pragma unroll
            for (int ni = 0; ni < 8; ni++) {
                uint32_t base = sB + b_row_off + (uint32_t)(ni * 8 * 64);
                b[ni][0] = lds32(base + ka0);
                b[ni][1] = lds32(base + ka1);
            }
            #pragma unroll
            for (int mi = 0; mi < 4; mi++)
                #pragma unroll
                for (int ni = 0; ni < 8; ni++)
                    mma_tf32(acc[mi][ni], a[mi], b[ni]);
        }
        __syncthreads();
        if (s + 3 < NS) load_stage(s + 3, buf);
        CP_COMMIT();
        buf = (buf == 2) ? 0 : buf + 1;
    }

    // ---- epilogue: registers -> global, fused ops
    #pragma unroll
    for (int mi = 0; mi < 4; mi++) {
        int r0 = m0 + wm*64 + mi*16 + (lane >> 2);
        #pragma unroll
        for (int ni = 0; ni < 8; ni++) {
            int c0 = n0 + wn*64 + ni*8 + (lane & 3)*2;
            float v0 = acc[mi][ni][0], v1 = acc[mi][ni][1];
            float v2 = acc[mi][ni][2], v3 = acc[mi][ni][3];
            if (EPI == EPI_SIGMOID) {
                v0 = 1.f/(1.f+__expf(-v0)); v1 = 1.f/(1.f+__expf(-v1));
                v2 = 1.f/(1.f+__expf(-v2)); v3 = 1.f/(1.f+__expf(-v3));
            } else if (EPI == EPI_RELUSQ) {
                v0 = fmaxf(v0,0.f); v1 = fmaxf(v1,0.f);
                v2 = fmaxf(v2,0.f); v3 = fmaxf(v3,0.f);
                v0 *= v0; v1 *= v1; v2 *= v2; v3 *= v3;
            }
            size_t i0 = (size_t)r0 * N + c0;
            size_t i1 = (size_t)(r0 + 8) * N + c0;
            if (EPI == EPI_RESID) {
                float2 rz0 = *(const float2*)(resid + i0);
                float2 rz1 = *(const float2*)(resid + i1);
                float2 gz0 = *(const float2*)(gate  + i0);
                float2 gz1 = *(const float2*)(gate  + i1);
                v0 = rz0.x + gz0.x*v0; v1 = rz0.y + gz0.y*v1;
                v2 = rz1.x + gz1.x*v2; v3 = rz1.y + gz1.y*v3;
            }
            *(float2*)(Cc + i0) = make_float2(v0, v1);
            *(float2*)(Cc + i1) = make_float2(v2, v3);
        }
    }
}

// ---------------------------------------------------------------------------
// Host launcher
// ---------------------------------------------------------------------------
static float* symaddr(const void* sym)
{
    void* p = nullptr;
    cudaGetSymbolAddress(&p, sym);
    return (float*)p;
}

extern "C" void kernel_launch(void* const* d_in, const int* in_sizes, int n_in,
                              void* d_out, int out_size)
{
    const float* x      = (const float*)d_in[0];
    const float* tdecay = (const float*)d_in[1];
    const float* tfirst = (const float*)d_in[2];
    const float* w_tk   = (const float*)d_in[3];
    const float* w_tv   = (const float*)d_in[4];
    const float* w_tr   = (const float*)d_in[5];
    const float* w_ck   = (const float*)d_in[6];
    const float* w_cv   = (const float*)d_in[7];
    const float* w_cr   = (const float*)d_in[8];
    const float* ln1_g  = (const float*)d_in[9];
    const float* ln1_b  = (const float*)d_in[10];
    const float* ln2_g  = (const float*)d_in[11];
    const float* ln2_b  = (const float*)d_in[12];
    const float* mix_k  = (const float*)d_in[13];
    const float* mix_v  = (const float*)d_in[14];
    const float* mix_r  = (const float*)d_in[15];
    const float* cmix_k = (const float*)d_in[16];
    const float* cmix_r = (const float*)d_in[17];
    float* out = (float*)d_out;

    float* h    = symaddr(g_h);
    float* xk   = symaddr(g_xk);
    float* xv   = symaddr(g_xv);
    float* xr   = symaddr(g_xr);
    float* k    = symaddr(g_k);
    float* v    = symaddr(g_v);
    float* r    = symaddr(g_r);
    float* x2   = symaddr(g_x2);
    float* h2   = symaddr(g_h2);
    float* ck   = symaddr(g_ck);
    float* cr   = symaddr(g_cr);
    float* s    = symaddr(g_s);
    float* kk   = symaddr(g_kk);
    float* wtkT = symaddr(g_wtkT);
    float* wtvT = symaddr(g_wtvT);
    float* wtrT = symaddr(g_wtrT);
    float* wcrT = symaddr(g_wcrT);
    float* wckT = symaddr(g_wckT);
    float* wcvT = symaddr(g_wcvT);

    cudaFuncSetAttribute((const void*)mma_gemm<EPI_NONE>,    cudaFuncAttributeMaxDynamicSharedMemorySize, GSMEM);
    cudaFuncSetAttribute((const void*)mma_gemm<EPI_SIGMOID>, cudaFuncAttributeMaxDynamicSharedMemorySize, GSMEM);
    cudaFuncSetAttribute((const void*)mma_gemm<EPI_RELUSQ>,  cudaFuncAttributeMaxDynamicSharedMemorySize, GSMEM);
    cudaFuncSetAttribute((const void*)mma_gemm<EPI_RESID>,   cudaFuncAttributeMaxDynamicSharedMemorySize, GSMEM);

    const int M = MROWS;
    dim3 tb(32, 8);

    // 0) transpose weights -> K-major B operands
    transpose_kernel<<<dim3(CC/32,   CC/32),   tb>>>(w_tk, wtkT, CC,   CC);
    transpose_kernel<<<dim3(CC/32,   CC/32),   tb>>>(w_tv, wtvT, CC,   CC);
    transpose_kernel<<<dim3(CC/32,   CC/32),   tb>>>(w_tr, wtrT, CC,   CC);
    transpose_kernel<<<dim3(CC/32,   CC/32),   tb>>>(w_cr, wcrT, CC,   CC);
    transpose_kernel<<<dim3(4*CC/32, CC/32),   tb>>>(w_ck, wckT, CC,   4*CC);
    transpose_kernel<<<dim3(CC/32,   4*CC/32), tb>>>(w_cv, wcvT, 4*CC, CC);

    dim3 gC (CC/CTN,   M/CTM);    // (8, 64)
    dim3 g4C(4*CC/CTN, M/CTM);    // (32, 64)
    const int mixg = (BTC/4) / 256;

    // 1) h = LN1(x)
    ln_kernel<<<M, 256>>>(x, ln1_g, ln1_b, h);

    // 2) token-shift mixes
    mix3_kernel<<<mixg, 256>>>(h, mix_k, mix_v, mix_r, xk, xv, xr);

    // 3) k, v, r GEMMs (r with sigmoid)
    mma_gemm<EPI_NONE>   <<<gC, 256, GSMEM>>>(xk, wtkT, k, nullptr, nullptr, M, CC, CC);
    mma_gemm<EPI_NONE>   <<<gC, 256, GSMEM>>>(xv, wtvT, v, nullptr, nullptr, M, CC, CC);
    mma_gemm<EPI_SIGMOID><<<gC, 256, GSMEM>>>(xr, wtrT, r, nullptr, nullptr, M, CC, CC);

    // 4) x2 = x + r * WKV(k, v)
    wkv_kernel<<<(MB * CC) / 256, 256>>>(k, v, r, x, tdecay, tfirst, x2);

    // 5) h2 = LN2(x2)
    ln_kernel<<<M, 256>>>(x2, ln2_g, ln2_b, h2);

    // 6) channel-mix shifts
    mix2_kernel<<<mixg, 256>>>(h2, cmix_k, cmix_r, ck, cr);

    // 7) kk = relu(ck @ w_ck)^2   [M, 4096]
    mma_gemm<EPI_RELUSQ> <<<g4C, 256, GSMEM>>>(ck, wckT, kk, nullptr, nullptr, M, 4*CC, CC);

    // 8) s = sigmoid(cr @ w_cr)
    mma_gemm<EPI_SIGMOID><<<gC, 256, GSMEM>>>(cr, wcrT, s, nullptr, nullptr, M, CC, CC);

    // 9) out = x2 + s * (kk @ w_cv)   [K = 4096]
    mma_gemm<EPI_RESID>  <<<gC, 256, GSMEM>>>(kk, wcvT, out, x2, s, M, CC, 4*CC);
}